// round 11
// baseline (speedup 1.0000x reference)
#include <cuda_runtime.h>
#include <cuda_fp16.h>
#include <cstdint>

#define B_ 4
#define T_ 4096
#define C_ 512
#define H_ 64
#define KST 72              // attn smem row stride (fp16 units)
#define QST 136             // qkv smem row stride (fp16 units, 272B)
#define SCALE2 0.06375873f  // 512^-0.5 * log2(e), folded into Wk/bk

// g_wt: [192][512] fp16, W^T, c-perm16, k-rows pre-scaled by SCALE2
// g_k/g_q: [B*T][64] fp16, h-perm16 (k pre-scaled)
// g_vT: [B][64][4096] fp16, transposed, j-perm16
__device__ __half g_wt[192 * 512];
__device__ __half g_k[B_ * T_ * H_];
__device__ __half g_q[B_ * T_ * H_];
__device__ __half g_vT[B_ * H_ * T_];

// ---------------------------------------------------------------------------
__device__ __forceinline__ int p16(int i) {
  return (i & ~15) | (((i >> 1) & 3) << 2) | (((i >> 3) & 1) << 1) | (i & 1);
}
__device__ __forceinline__ unsigned ex2h2(unsigned x) {
  unsigned r;
  asm("ex2.approx.f16x2 %0, %1;" : "=r"(r) : "r"(x));
  return r;
}
__device__ __forceinline__ unsigned hadd2u(unsigned a, unsigned b) {
  unsigned r;
  asm("add.f16x2 %0, %1, %2;" : "=r"(r) : "r"(a), "r"(b));
  return r;
}
__device__ __forceinline__ void mma_f16(float d[4], unsigned a0, unsigned a1,
                                        unsigned a2, unsigned a3, unsigned b0,
                                        unsigned b1) {
  asm volatile(
      "mma.sync.aligned.m16n8k16.row.col.f32.f16.f16.f32 "
      "{%0,%1,%2,%3}, {%4,%5,%6,%7}, {%8,%9}, {%0,%1,%2,%3};"
      : "+f"(d[0]), "+f"(d[1]), "+f"(d[2]), "+f"(d[3])
      : "r"(a0), "r"(a1), "r"(a2), "r"(a3), "r"(b0), "r"(b1));
}
__device__ __forceinline__ void mma_f16h(unsigned d[2], unsigned a0,
                                         unsigned a1, unsigned a2, unsigned a3,
                                         unsigned b0, unsigned b1) {
  asm volatile(
      "mma.sync.aligned.m16n8k16.row.col.f16.f16.f16.f16 "
      "{%0,%1}, {%2,%3,%4,%5}, {%6,%7}, {%0,%1};"
      : "+r"(d[0]), "+r"(d[1])
      : "r"(a0), "r"(a1), "r"(a2), "r"(a3), "r"(b0), "r"(b1));
}

#define CP16(dst_u32, src_ptr) \
  asm volatile("cp.async.cg.shared.global [%0], [%1], 16;\n" ::"r"(dst_u32), "l"(src_ptr))
#define CPCOMMIT asm volatile("cp.async.commit_group;\n")
#define CPWAIT0 asm volatile("cp.async.wait_group 0;\n")

__device__ __forceinline__ uint32_t smem_u32(const void* p) {
  return (uint32_t)__cvta_generic_to_shared(p);
}

// ---------------------------------------------------------------------------
// Prep: W^T fp16, c-perm16, scale-fold for k. Tiled smem transpose,
// 16c x 64n tiles -> grid = 3 mats x 32 c-tiles = 96 blocks.
// Reads: coalesced 256B rows. Writes: contiguous 32B segments per n-row
// (p16 permutes only within 16-aligned groups = exactly one tile's c-range).
// ---------------------------------------------------------------------------
__global__ void prep_w_kernel(const float* __restrict__ Wk,
                              const float* __restrict__ Wq,
                              const float* __restrict__ Wv) {
  __shared__ float ws[16][65];
  const int mat = blockIdx.x >> 5;
  const int ct = blockIdx.x & 31;
  const float* W = (mat == 0) ? Wk : ((mat == 1) ? Wq : Wv);
  const float s = (mat == 0) ? SCALE2 : 1.0f;
  const int tid = threadIdx.x;

  // load 16 c-rows x 64 n, fully coalesced (4 rows per 256-thread pass)
  #pragma unroll
  for (int i = tid; i < 1024; i += 256) {
    int c = i >> 6, n = i & 63;
    ws[c][n] = W[(size_t)(ct * 16 + c) * H_ + n] * s;
  }
  __syncthreads();

  // write transposed: for each n, 16 c values -> one 32B contiguous segment
  const int cbase = ct * 16;
  #pragma unroll
  for (int i = tid; i < 1024; i += 256) {
    int n = i >> 4, cl = i & 15;
    g_wt[(size_t)(mat * 64 + n) * 512 + cbase + p16(cl)] =
        __float2half(ws[cl][n]);
  }
}

// ---------------------------------------------------------------------------
// QKV: M=16384, N=192, K=512, fp16 mma. BK=128 (4 chunks), double-buffered.
// (identical to R9/R10)
// ---------------------------------------------------------------------------
#define QKV_BUF_HALFS (128 * QST + 192 * QST)
#define QKV_SMEM_BYTES (2 * QKV_BUF_HALFS * 2)

__global__ __launch_bounds__(256) void qkv_kernel(
    const float* __restrict__ x,
    const float* __restrict__ bk, const float* __restrict__ bq,
    const float* __restrict__ bv) {
  extern __shared__ __half hsm[];

  const int row0 = blockIdx.x * 128;
  const int tid = threadIdx.x;
  const int w = tid >> 5;
  const int lane = tid & 31;
  const int g = lane >> 2;
  const int t = lane & 3;

  auto ldg_part = [&](int kc, int p, float4* xr) {
    #pragma unroll
    for (int j = 0; j < 8; j++) {
      int i = tid + (p * 8 + j) * 256;
      int r = i >> 5, l = (i & 31) * 4;
      xr[j] = *(const float4*)&x[(size_t)(row0 + r) * C_ + kc + l];
    }
  };
  auto sts_part = [&](int buf, int p, const float4* xr) {
    __half* xb = hsm + buf * QKV_BUF_HALFS;
    #pragma unroll
    for (int j = 0; j < 8; j++) {
      int i = tid + (p * 8 + j) * 256;
      int r = i >> 5, l = (i & 31) * 4;
      int p0 = p16(l);
      *(__half2*)&xb[r * QST + p0]     = __floats2half2_rn(xr[j].x, xr[j].y);
      *(__half2*)&xb[r * QST + p0 + 4] = __floats2half2_rn(xr[j].z, xr[j].w);
    }
  };
  auto cp_w = [&](int kc, int buf) {
    __half* wb = hsm + buf * QKV_BUF_HALFS + 128 * QST;
    #pragma unroll
    for (int i = tid; i < 192 * 16; i += 256) {
      int r = i >> 4, ch = i & 15;
      CP16(smem_u32(&wb[r * QST + ch * 8]), g_wt + r * 512 + kc + ch * 8);
    }
  };

  {
    float4 xr[8];
    cp_w(0, 0);
    CPCOMMIT;
    ldg_part(0, 0, xr);
    sts_part(0, 0, xr);
    ldg_part(0, 1, xr);
    sts_part(0, 1, xr);
    CPWAIT0;
  }
  __syncthreads();

  float acc[24][4] = {};

  for (int ci = 0; ci < 4; ci++) {
    const int cur = ci & 1, nxt = cur ^ 1;
    const int kcn = (ci + 1) * 128;
    float4 xr[8];
    if (ci < 3) {
      cp_w(kcn, nxt);
      CPCOMMIT;
      ldg_part(kcn, 0, xr);
    }

    const __half* xb = hsm + cur * QKV_BUF_HALFS;
    const __half* wb = xb + 128 * QST;
    #pragma unroll
    for (int kk = 0; kk < 4; kk++) {
      const __half* ab = xb + (16 * w + g) * QST + 16 * kk + 4 * t;
      uint2 u0 = *(const uint2*)ab;
      uint2 u1 = *(const uint2*)(ab + 8 * QST);
      #pragma unroll
      for (int nt = 0; nt < 24; nt++) {
        uint2 bb2 = *(const uint2*)(wb + (8 * nt + g) * QST + 16 * kk + 4 * t);
        mma_f16(acc[nt], u0.x, u1.x, u0.y, u1.y, bb2.x, bb2.y);
      }
    }

    if (ci < 3) {
      sts_part(nxt, 0, xr);
      ldg_part(kcn, 1, xr);
    }

    #pragma unroll
    for (int kk = 4; kk < 8; kk++) {
      const __half* ab = xb + (16 * w + g) * QST + 16 * kk + 4 * t;
      uint2 u0 = *(const uint2*)ab;
      uint2 u1 = *(const uint2*)(ab + 8 * QST);
      #pragma unroll
      for (int nt = 0; nt < 24; nt++) {
        uint2 bb2 = *(const uint2*)(wb + (8 * nt + g) * QST + 16 * kk + 4 * t);
        mma_f16(acc[nt], u0.x, u1.x, u0.y, u1.y, bb2.x, bb2.y);
      }
    }

    if (ci < 3) {
      sts_part(nxt, 1, xr);
      CPWAIT0;
    }
    __syncthreads();
  }

  const int rA = row0 + 16 * w + g;
  const int rB = rA + 8;
  #pragma unroll
  for (int nt = 0; nt < 24; nt++) {
    int mat = nt >> 3;
    int nn = (nt & 7) * 8 + 2 * t;
    const float* bias = (mat == 0) ? bk : ((mat == 1) ? bq : bv);
    float s = (mat == 0) ? SCALE2 : 1.0f;
    float b0 = bias[nn] * s, b1 = bias[nn + 1] * s;
    float v00 = acc[nt][0] + b0, v01 = acc[nt][1] + b1;
    float v10 = acc[nt][2] + b0, v11 = acc[nt][3] + b1;
    if (mat < 2) {
      __half* outm = (mat == 0) ? g_k : g_q;
      int cA = p16(nn), cB = p16(nn + 1);
      outm[(size_t)rA * H_ + cA] = __float2half(v00);
      outm[(size_t)rA * H_ + cB] = __float2half(v01);
      outm[(size_t)rB * H_ + cA] = __float2half(v10);
      outm[(size_t)rB * H_ + cB] = __float2half(v11);
    } else {
      int bb = rA >> 12;
      int jA = p16(rA & 4095), jB = p16(rB & 4095);
      g_vT[((size_t)bb * H_ + nn) * T_ + jA]     = __float2half(v00);
      g_vT[((size_t)bb * H_ + nn + 1) * T_ + jA] = __float2half(v01);
      g_vT[((size_t)bb * H_ + nn) * T_ + jB]     = __float2half(v10);
      g_vT[((size_t)bb * H_ + nn + 1) * T_ + jB] = __float2half(v11);
    }
  }
}

// ---------------------------------------------------------------------------
// Attention (identical to R7/R9/R10): BR=128 k-rows, 8 warps = 4 wm x 2 wn.
// ---------------------------------------------------------------------------
#define KS_H 0
#define Q0_H (128 * KST)
#define Q1_H (Q0_H + 64 * KST)
#define V0_H (Q1_H + 64 * KST)
#define V1_H (V0_H + 64 * KST)
#define ATTN_SMEM_BYTES ((V1_H + 64 * KST) * 2)
#define NT_ (T_ / 64)

__global__ __launch_bounds__(256) void attn_kernel(float* __restrict__ out) {
  extern __shared__ __half hsm[];
  float* fsm = reinterpret_cast<float*>(hsm);

  const int b = blockIdx.y;
  const int row0 = blockIdx.x * 128;
  const int tid = threadIdx.x;
  const int w = tid >> 5;
  const int wm = w >> 1;
  const int wn = w & 1;
  const int lane = tid & 31;
  const int g = lane >> 2;
  const int t = lane & 3;

  const __half* kg = g_k + (size_t)(b * T_ + row0) * H_;
  const __half* qg = g_q + (size_t)b * T_ * H_;
  const __half* vg = g_vT + (size_t)b * H_ * T_;

  auto load_tile = [&](int jt, int buf) {
    const int qo = buf ? Q1_H : Q0_H;
    const int vo = buf ? V1_H : V0_H;
    #pragma unroll
    for (int i = tid; i < 1024; i += 256) {
      if (i < 512) {
        int r = i >> 3, ch = i & 7;
        CP16(smem_u32(&hsm[qo + r * KST + ch * 8]),
             qg + (size_t)(jt + r) * H_ + ch * 8);
      } else {
        int r = (i - 512) >> 3, ch = i & 7;
        CP16(smem_u32(&hsm[vo + r * KST + ch * 8]),
             vg + (size_t)r * T_ + jt + ch * 8);
      }
    }
  };

  #pragma unroll
  for (int i = tid; i < 1024; i += 256) {
    int r = i >> 3, ch = i & 7;
    CP16(smem_u32(&hsm[KS_H + r * KST + ch * 8]),
         kg + (size_t)r * H_ + ch * 8);
  }
  load_tile(0, 0);
  CPCOMMIT;
  CPWAIT0;
  __syncthreads();

  unsigned kfa[2][4][4];
  #pragma unroll
  for (int mt2 = 0; mt2 < 2; mt2++)
    #pragma unroll
    for (int kk = 0; kk < 4; kk++) {
      const __half* base =
          hsm + KS_H + (32 * wm + 16 * mt2 + g) * KST + 16 * kk + 4 * t;
      uint2 u0 = *(const uint2*)base;
      uint2 u1 = *(const uint2*)(base + 8 * KST);
      kfa[mt2][kk][0] = u0.x;
      kfa[mt2][kk][1] = u1.x;
      kfa[mt2][kk][2] = u0.y;
      kfa[mt2][kk][3] = u1.y;
    }

  float l[4] = {};
  float oc[4][4][4] = {};

  for (int it = 0; it < NT_; ++it) {
    if (it + 1 < NT_) {
      load_tile((it + 1) * 64, (it + 1) & 1);
      CPCOMMIT;
    }
    const __half* qs = hsm + ((it & 1) ? Q1_H : Q0_H);
    const __half* vs = hsm + ((it & 1) ? V1_H : V0_H);

    unsigned sch[2][4][2] = {};
    #pragma unroll
    for (int kk = 0; kk < 4; kk++) {
      #pragma unroll
      for (int nt = 0; nt < 4; nt++) {
        uint2 qb =
            *(const uint2*)(qs + (32 * wn + 8 * nt + g) * KST + 16 * kk + 4 * t);
        mma_f16h(sch[0][nt], kfa[0][kk][0], kfa[0][kk][1], kfa[0][kk][2],
                 kfa[0][kk][3], qb.x, qb.y);
        mma_f16h(sch[1][nt], kfa[1][kk][0], kfa[1][kk][1], kfa[1][kk][2],
                 kfa[1][kk][3], qb.x, qb.y);
      }
    }

    unsigned lh[4] = {0u, 0u, 0u, 0u};
    #pragma unroll
    for (int mt2 = 0; mt2 < 2; mt2++)
      #pragma unroll
      for (int nt = 0; nt < 4; nt++)
        #pragma unroll
        for (int dj = 0; dj < 2; dj++) {
          unsigned p = ex2h2(sch[mt2][nt][dj]);
          sch[mt2][nt][dj] = p;
          lh[2 * mt2 + dj] = hadd2u(lh[2 * mt2 + dj], p);
        }
    #pragma unroll
    for (int i = 0; i < 4; i++) {
      float2 f = __half22float2(*reinterpret_cast<__half2*>(&lh[i]));
      l[i] += f.x + f.y;
    }

    #pragma unroll
    for (int mt = 0; mt < 4; mt++)
      #pragma unroll
      for (int kk2 = 0; kk2 < 2; kk2++) {
        const __half* ab = vs + (16 * mt + g) * KST + 32 * wn + 16 * kk2 + 4 * t;
        uint2 va = *(const uint2*)ab;
        uint2 vb2 = *(const uint2*)(ab + 8 * KST);
        #pragma unroll
        for (int ntt = 0; ntt < 4; ntt++)
          mma_f16(oc[mt][ntt], va.x, vb2.x, va.y, vb2.y,
                  sch[ntt >> 1][2 * kk2][ntt & 1],
                  sch[ntt >> 1][2 * kk2 + 1][ntt & 1]);
      }

    if (it + 1 < NT_) {
      CPWAIT0;
      __syncthreads();
    }
  }

  __syncthreads();
  float* Om = fsm;
  float* ls = fsm + 8192;

  #pragma unroll
  for (int i = 0; i < 4; i++) {
    l[i] += __shfl_xor_sync(0xffffffffu, l[i], 1);
    l[i] += __shfl_xor_sync(0xffffffffu, l[i], 2);
  }
  if (t == 0) {
    #pragma unroll
    for (int i = 0; i < 4; i++)
      ls[wn * 128 + 32 * wm + 16 * (i >> 1) + 8 * (i & 1) + g] = l[i];
  }
  if (wn == 1) {
    #pragma unroll
    for (int mt = 0; mt < 4; mt++)
      #pragma unroll
      for (int ntt = 0; ntt < 4; ntt++) {
        int hi = 16 * mt + g, kr = 8 * ntt + 2 * t;
        Om[wm * 2048 + hi * 32 + kr]           = oc[mt][ntt][0];
        Om[wm * 2048 + hi * 32 + kr + 1]       = oc[mt][ntt][1];
        Om[wm * 2048 + (hi + 8) * 32 + kr]     = oc[mt][ntt][2];
        Om[wm * 2048 + (hi + 8) * 32 + kr + 1] = oc[mt][ntt][3];
      }
  }
  __syncthreads();

  if (wn == 0) {
    float inv[4][2];
    #pragma unroll
    for (int ntt = 0; ntt < 4; ntt++) {
      int r = 32 * wm + 8 * ntt + 2 * t;
      inv[ntt][0] = 1.0f / (ls[r] + ls[128 + r]);
      inv[ntt][1] = 1.0f / (ls[r + 1] + ls[128 + r + 1]);
    }
    const size_t obase = ((size_t)b * T_ + row0 + 32 * wm) * H_;
    #pragma unroll
    for (int mt = 0; mt < 4; mt++)
      #pragma unroll
      for (int ntt = 0; ntt < 4; ntt++) {
        int hi = 16 * mt + g, kr = 8 * ntt + 2 * t;
        float v0 = (oc[mt][ntt][0] + Om[wm * 2048 + hi * 32 + kr]) * inv[ntt][0];
        float v1 = (oc[mt][ntt][1] + Om[wm * 2048 + hi * 32 + kr + 1]) * inv[ntt][1];
        float v2 = (oc[mt][ntt][2] + Om[wm * 2048 + (hi + 8) * 32 + kr]) * inv[ntt][0];
        float v3 = (oc[mt][ntt][3] + Om[wm * 2048 + (hi + 8) * 32 + kr + 1]) * inv[ntt][1];
        out[obase + (size_t)kr * H_ + hi]           = v0;
        out[obase + (size_t)(kr + 1) * H_ + hi]     = v1;
        out[obase + (size_t)kr * H_ + hi + 8]       = v2;
        out[obase + (size_t)(kr + 1) * H_ + hi + 8] = v3;
      }
  }
}

extern "C" void kernel_launch(void* const* d_in, const int* in_sizes, int n_in,
                              void* d_out, int out_size) {
  const float* x  = (const float*)d_in[0];
  const float* Wk = (const float*)d_in[1];
  const float* bk = (const float*)d_in[2];
  const float* Wq = (const float*)d_in[3];
  const float* bq = (const float*)d_in[4];
  const float* Wv = (const float*)d_in[5];
  const float* bv = (const float*)d_in[6];
  float* out = (float*)d_out;

  static bool attr_set = false;
  if (!attr_set) {
    cudaFuncSetAttribute(qkv_kernel, cudaFuncAttributeMaxDynamicSharedMemorySize,
                         QKV_SMEM_BYTES);
    cudaFuncSetAttribute(attn_kernel, cudaFuncAttributeMaxDynamicSharedMemorySize,
                         ATTN_SMEM_BYTES);
    attr_set = true;
  }

  prep_w_kernel<<<96, 256>>>(Wk, Wq, Wv);
  qkv_kernel<<<(B_ * T_) / 128, 256, QKV_SMEM_BYTES>>>(x, bk, bq, bv);
  dim3 attn_grid(T_ / 128, B_);
  attn_kernel<<<attn_grid, 256, ATTN_SMEM_BYTES>>>(out);
}

// round 12
// speedup vs baseline: 1.5508x; 1.5508x over previous
#include <cuda_runtime.h>
#include <cuda_fp16.h>
#include <cstdint>

#define B_ 4
#define T_ 4096
#define C_ 512
#define H_ 64
#define KST 72              // attn smem row stride (fp16 units)
#define QST 136             // qkv smem row stride (fp16 units, 272B)
#define SCALE2 0.06375873f  // 512^-0.5 * log2(e), folded into Wk/bk

// g_wt: [192][512] fp16, W^T, c-perm16, k-rows pre-scaled by SCALE2
// g_k/g_q: [B*T][64] fp16, h-perm16 (k pre-scaled)
// g_vT: [B][64][4096] fp16, transposed, j-perm16
__device__ __half g_wt[192 * 512];
__device__ __half g_k[B_ * T_ * H_];
__device__ __half g_q[B_ * T_ * H_];
__device__ __half g_vT[B_ * H_ * T_];

// ---------------------------------------------------------------------------
__device__ __forceinline__ int p16(int i) {
  return (i & ~15) | (((i >> 1) & 3) << 2) | (((i >> 3) & 1) << 1) | (i & 1);
}
__device__ __forceinline__ unsigned ex2h2(unsigned x) {
  unsigned r;
  asm("ex2.approx.f16x2 %0, %1;" : "=r"(r) : "r"(x));
  return r;
}
__device__ __forceinline__ unsigned hadd2u(unsigned a, unsigned b) {
  unsigned r;
  asm("add.f16x2 %0, %1, %2;" : "=r"(r) : "r"(a), "r"(b));
  return r;
}
__device__ __forceinline__ void mma_f16(float d[4], unsigned a0, unsigned a1,
                                        unsigned a2, unsigned a3, unsigned b0,
                                        unsigned b1) {
  asm volatile(
      "mma.sync.aligned.m16n8k16.row.col.f32.f16.f16.f32 "
      "{%0,%1,%2,%3}, {%4,%5,%6,%7}, {%8,%9}, {%0,%1,%2,%3};"
      : "+f"(d[0]), "+f"(d[1]), "+f"(d[2]), "+f"(d[3])
      : "r"(a0), "r"(a1), "r"(a2), "r"(a3), "r"(b0), "r"(b1));
}
__device__ __forceinline__ void mma_f16h(unsigned d[2], unsigned a0,
                                         unsigned a1, unsigned a2, unsigned a3,
                                         unsigned b0, unsigned b1) {
  asm volatile(
      "mma.sync.aligned.m16n8k16.row.col.f16.f16.f16.f16 "
      "{%0,%1}, {%2,%3,%4,%5}, {%6,%7}, {%0,%1};"
      : "+r"(d[0]), "+r"(d[1])
      : "r"(a0), "r"(a1), "r"(a2), "r"(a3), "r"(b0), "r"(b1));
}

#define CP16(dst_u32, src_ptr) \
  asm volatile("cp.async.cg.shared.global [%0], [%1], 16;\n" ::"r"(dst_u32), "l"(src_ptr))
#define CPCOMMIT asm volatile("cp.async.commit_group;\n")
#define CPWAIT0 asm volatile("cp.async.wait_group 0;\n")

__device__ __forceinline__ uint32_t smem_u32(const void* p) {
  return (uint32_t)__cvta_generic_to_shared(p);
}

// ---------------------------------------------------------------------------
// Prep: W^T fp16, c-perm16, scale-fold for k. Tiled smem transpose:
// coalesced float reads of W, near-contiguous fp16 writes of g_wt.
// grid = 3 mats x 8 c-tiles = 24 blocks.
// ---------------------------------------------------------------------------
__global__ void prep_w_kernel(const float* __restrict__ Wk,
                              const float* __restrict__ Wq,
                              const float* __restrict__ Wv) {
  __shared__ float ws[64][65];
  const int mat = blockIdx.x >> 3;
  const int ct = blockIdx.x & 7;
  const float* W = (mat == 0) ? Wk : ((mat == 1) ? Wq : Wv);
  const float s = (mat == 0) ? SCALE2 : 1.0f;
  const int tid = threadIdx.x;

  // load 64 c-rows x 64 n, fully coalesced
  #pragma unroll
  for (int i = tid; i < 4096; i += 256) {
    int c = i >> 6, n = i & 63;
    ws[c][n] = W[(size_t)(ct * 64 + c) * H_ + n] * s;
  }
  __syncthreads();

  // write transposed: row n of g_wt, 64 c values (p16-permuted within 16s)
  const int cbase = ct * 64;
  #pragma unroll
  for (int i = tid; i < 1024; i += 256) {
    int n = i >> 4, c4 = (i & 15) * 4;
    __half* dst = &g_wt[(size_t)(mat * 64 + n) * 512 + cbase];
    #pragma unroll
    for (int j = 0; j < 4; j++) {
      int c = c4 + j;
      dst[p16(c)] = __float2half(ws[c][n]);
    }
  }
}

// ---------------------------------------------------------------------------
// QKV: M=16384, N=192, K=512, fp16 mma. BK=128 (4 chunks), double-buffered.
// ---------------------------------------------------------------------------
#define QKV_BUF_HALFS (128 * QST + 192 * QST)
#define QKV_SMEM_BYTES (2 * QKV_BUF_HALFS * 2)

__global__ __launch_bounds__(256) void qkv_kernel(
    const float* __restrict__ x,
    const float* __restrict__ bk, const float* __restrict__ bq,
    const float* __restrict__ bv) {
  extern __shared__ __half hsm[];

  const int row0 = blockIdx.x * 128;
  const int tid = threadIdx.x;
  const int w = tid >> 5;
  const int lane = tid & 31;
  const int g = lane >> 2;
  const int t = lane & 3;

  auto ldg_part = [&](int kc, int p, float4* xr) {
    #pragma unroll
    for (int j = 0; j < 8; j++) {
      int i = tid + (p * 8 + j) * 256;
      int r = i >> 5, l = (i & 31) * 4;
      xr[j] = *(const float4*)&x[(size_t)(row0 + r) * C_ + kc + l];
    }
  };
  auto sts_part = [&](int buf, int p, const float4* xr) {
    __half* xb = hsm + buf * QKV_BUF_HALFS;
    #pragma unroll
    for (int j = 0; j < 8; j++) {
      int i = tid + (p * 8 + j) * 256;
      int r = i >> 5, l = (i & 31) * 4;
      int p0 = p16(l);
      *(__half2*)&xb[r * QST + p0]     = __floats2half2_rn(xr[j].x, xr[j].y);
      *(__half2*)&xb[r * QST + p0 + 4] = __floats2half2_rn(xr[j].z, xr[j].w);
    }
  };
  auto cp_w = [&](int kc, int buf) {
    __half* wb = hsm + buf * QKV_BUF_HALFS + 128 * QST;
    #pragma unroll
    for (int i = tid; i < 192 * 16; i += 256) {
      int r = i >> 4, ch = i & 15;
      CP16(smem_u32(&wb[r * QST + ch * 8]), g_wt + r * 512 + kc + ch * 8);
    }
  };

  {
    float4 xr[8];
    cp_w(0, 0);
    CPCOMMIT;
    ldg_part(0, 0, xr);
    sts_part(0, 0, xr);
    ldg_part(0, 1, xr);
    sts_part(0, 1, xr);
    CPWAIT0;
  }
  __syncthreads();

  float acc[24][4] = {};

  for (int ci = 0; ci < 4; ci++) {
    const int cur = ci & 1, nxt = cur ^ 1;
    const int kcn = (ci + 1) * 128;
    float4 xr[8];
    if (ci < 3) {
      cp_w(kcn, nxt);
      CPCOMMIT;
      ldg_part(kcn, 0, xr);
    }

    const __half* xb = hsm + cur * QKV_BUF_HALFS;
    const __half* wb = xb + 128 * QST;
    #pragma unroll
    for (int kk = 0; kk < 4; kk++) {
      const __half* ab = xb + (16 * w + g) * QST + 16 * kk + 4 * t;
      uint2 u0 = *(const uint2*)ab;
      uint2 u1 = *(const uint2*)(ab + 8 * QST);
      #pragma unroll
      for (int nt = 0; nt < 24; nt++) {
        uint2 bb2 = *(const uint2*)(wb + (8 * nt + g) * QST + 16 * kk + 4 * t);
        mma_f16(acc[nt], u0.x, u1.x, u0.y, u1.y, bb2.x, bb2.y);
      }
    }

    if (ci < 3) {
      sts_part(nxt, 0, xr);
      ldg_part(kcn, 1, xr);
    }

    #pragma unroll
    for (int kk = 4; kk < 8; kk++) {
      const __half* ab = xb + (16 * w + g) * QST + 16 * kk + 4 * t;
      uint2 u0 = *(const uint2*)ab;
      uint2 u1 = *(const uint2*)(ab + 8 * QST);
      #pragma unroll
      for (int nt = 0; nt < 24; nt++) {
        uint2 bb2 = *(const uint2*)(wb + (8 * nt + g) * QST + 16 * kk + 4 * t);
        mma_f16(acc[nt], u0.x, u1.x, u0.y, u1.y, bb2.x, bb2.y);
      }
    }

    if (ci < 3) {
      sts_part(nxt, 1, xr);
      CPWAIT0;
    }
    __syncthreads();
  }

  const int rA = row0 + 16 * w + g;
  const int rB = rA + 8;
  #pragma unroll
  for (int nt = 0; nt < 24; nt++) {
    int mat = nt >> 3;
    int nn = (nt & 7) * 8 + 2 * t;
    const float* bias = (mat == 0) ? bk : ((mat == 1) ? bq : bv);
    float s = (mat == 0) ? SCALE2 : 1.0f;
    float b0 = bias[nn] * s, b1 = bias[nn + 1] * s;
    float v00 = acc[nt][0] + b0, v01 = acc[nt][1] + b1;
    float v10 = acc[nt][2] + b0, v11 = acc[nt][3] + b1;
    if (mat < 2) {
      __half* outm = (mat == 0) ? g_k : g_q;
      int cA = p16(nn), cB = p16(nn + 1);
      outm[(size_t)rA * H_ + cA] = __float2half(v00);
      outm[(size_t)rA * H_ + cB] = __float2half(v01);
      outm[(size_t)rB * H_ + cA] = __float2half(v10);
      outm[(size_t)rB * H_ + cB] = __float2half(v11);
    } else {
      int bb = rA >> 12;
      int jA = p16(rA & 4095), jB = p16(rB & 4095);
      g_vT[((size_t)bb * H_ + nn) * T_ + jA]     = __float2half(v00);
      g_vT[((size_t)bb * H_ + nn + 1) * T_ + jA] = __float2half(v01);
      g_vT[((size_t)bb * H_ + nn) * T_ + jB]     = __float2half(v10);
      g_vT[((size_t)bb * H_ + nn + 1) * T_ + jB] = __float2half(v11);
    }
  }
}

// ---------------------------------------------------------------------------
// Attention: BR=128 k-rows, 8 warps = 4 wm x 2 wn.
// ---------------------------------------------------------------------------
#define KS_H 0
#define Q0_H (128 * KST)
#define Q1_H (Q0_H + 64 * KST)
#define V0_H (Q1_H + 64 * KST)
#define V1_H (V0_H + 64 * KST)
#define ATTN_SMEM_BYTES ((V1_H + 64 * KST) * 2)
#define NT_ (T_ / 64)

__global__ __launch_bounds__(256) void attn_kernel(float* __restrict__ out) {
  extern __shared__ __half hsm[];
  float* fsm = reinterpret_cast<float*>(hsm);

  const int b = blockIdx.y;
  const int row0 = blockIdx.x * 128;
  const int tid = threadIdx.x;
  const int w = tid >> 5;
  const int wm = w >> 1;
  const int wn = w & 1;
  const int lane = tid & 31;
  const int g = lane >> 2;
  const int t = lane & 3;

  const __half* kg = g_k + (size_t)(b * T_ + row0) * H_;
  const __half* qg = g_q + (size_t)b * T_ * H_;
  const __half* vg = g_vT + (size_t)b * H_ * T_;

  auto load_tile = [&](int jt, int buf) {
    const int qo = buf ? Q1_H : Q0_H;
    const int vo = buf ? V1_H : V0_H;
    #pragma unroll
    for (int i = tid; i < 1024; i += 256) {
      if (i < 512) {
        int r = i >> 3, ch = i & 7;
        CP16(smem_u32(&hsm[qo + r * KST + ch * 8]),
             qg + (size_t)(jt + r) * H_ + ch * 8);
      } else {
        int r = (i - 512) >> 3, ch = i & 7;
        CP16(smem_u32(&hsm[vo + r * KST + ch * 8]),
             vg + (size_t)r * T_ + jt + ch * 8);
      }
    }
  };

  #pragma unroll
  for (int i = tid; i < 1024; i += 256) {
    int r = i >> 3, ch = i & 7;
    CP16(smem_u32(&hsm[KS_H + r * KST + ch * 8]),
         kg + (size_t)r * H_ + ch * 8);
  }
  load_tile(0, 0);
  CPCOMMIT;
  CPWAIT0;
  __syncthreads();

  unsigned kfa[2][4][4];
  #pragma unroll
  for (int mt2 = 0; mt2 < 2; mt2++)
    #pragma unroll
    for (int kk = 0; kk < 4; kk++) {
      const __half* base =
          hsm + KS_H + (32 * wm + 16 * mt2 + g) * KST + 16 * kk + 4 * t;
      uint2 u0 = *(const uint2*)base;
      uint2 u1 = *(const uint2*)(base + 8 * KST);
      kfa[mt2][kk][0] = u0.x;
      kfa[mt2][kk][1] = u1.x;
      kfa[mt2][kk][2] = u0.y;
      kfa[mt2][kk][3] = u1.y;
    }

  float l[4] = {};
  float oc[4][4][4] = {};

  for (int it = 0; it < NT_; ++it) {
    if (it + 1 < NT_) {
      load_tile((it + 1) * 64, (it + 1) & 1);
      CPCOMMIT;
    }
    const __half* qs = hsm + ((it & 1) ? Q1_H : Q0_H);
    const __half* vs = hsm + ((it & 1) ? V1_H : V0_H);

    unsigned sch[2][4][2] = {};
    #pragma unroll
    for (int kk = 0; kk < 4; kk++) {
      #pragma unroll
      for (int nt = 0; nt < 4; nt++) {
        uint2 qb =
            *(const uint2*)(qs + (32 * wn + 8 * nt + g) * KST + 16 * kk + 4 * t);
        mma_f16h(sch[0][nt], kfa[0][kk][0], kfa[0][kk][1], kfa[0][kk][2],
                 kfa[0][kk][3], qb.x, qb.y);
        mma_f16h(sch[1][nt], kfa[1][kk][0], kfa[1][kk][1], kfa[1][kk][2],
                 kfa[1][kk][3], qb.x, qb.y);
      }
    }

    unsigned lh[4] = {0u, 0u, 0u, 0u};
    #pragma unroll
    for (int mt2 = 0; mt2 < 2; mt2++)
      #pragma unroll
      for (int nt = 0; nt < 4; nt++)
        #pragma unroll
        for (int dj = 0; dj < 2; dj++) {
          unsigned p = ex2h2(sch[mt2][nt][dj]);
          sch[mt2][nt][dj] = p;
          lh[2 * mt2 + dj] = hadd2u(lh[2 * mt2 + dj], p);
        }
    #pragma unroll
    for (int i = 0; i < 4; i++) {
      float2 f = __half22float2(*reinterpret_cast<__half2*>(&lh[i]));
      l[i] += f.x + f.y;
    }

    #pragma unroll
    for (int mt = 0; mt < 4; mt++)
      #pragma unroll
      for (int kk2 = 0; kk2 < 2; kk2++) {
        const __half* ab = vs + (16 * mt + g) * KST + 32 * wn + 16 * kk2 + 4 * t;
        uint2 va = *(const uint2*)ab;
        uint2 vb2 = *(const uint2*)(ab + 8 * KST);
        #pragma unroll
        for (int ntt = 0; ntt < 4; ntt++)
          mma_f16(oc[mt][ntt], va.x, vb2.x, va.y, vb2.y,
                  sch[ntt >> 1][2 * kk2][ntt & 1],
                  sch[ntt >> 1][2 * kk2 + 1][ntt & 1]);
      }

    if (it + 1 < NT_) {
      CPWAIT0;
      __syncthreads();
    }
  }

  __syncthreads();
  float* Om = fsm;
  float* ls = fsm + 8192;

  #pragma unroll
  for (int i = 0; i < 4; i++) {
    l[i] += __shfl_xor_sync(0xffffffffu, l[i], 1);
    l[i] += __shfl_xor_sync(0xffffffffu, l[i], 2);
  }
  if (t == 0) {
    #pragma unroll
    for (int i = 0; i < 4; i++)
      ls[wn * 128 + 32 * wm + 16 * (i >> 1) + 8 * (i & 1) + g] = l[i];
  }
  if (wn == 1) {
    #pragma unroll
    for (int mt = 0; mt < 4; mt++)
      #pragma unroll
      for (int ntt = 0; ntt < 4; ntt++) {
        int hi = 16 * mt + g, kr = 8 * ntt + 2 * t;
        Om[wm * 2048 + hi * 32 + kr]           = oc[mt][ntt][0];
        Om[wm * 2048 + hi * 32 + kr + 1]       = oc[mt][ntt][1];
        Om[wm * 2048 + (hi + 8) * 32 + kr]     = oc[mt][ntt][2];
        Om[wm * 2048 + (hi + 8) * 32 + kr + 1] = oc[mt][ntt][3];
      }
  }
  __syncthreads();

  if (wn == 0) {
    float inv[4][2];
    #pragma unroll
    for (int ntt = 0; ntt < 4; ntt++) {
      int r = 32 * wm + 8 * ntt + 2 * t;
      inv[ntt][0] = 1.0f / (ls[r] + ls[128 + r]);
      inv[ntt][1] = 1.0f / (ls[r + 1] + ls[128 + r + 1]);
    }
    const size_t obase = ((size_t)b * T_ + row0 + 32 * wm) * H_;
    #pragma unroll
    for (int mt = 0; mt < 4; mt++)
      #pragma unroll
      for (int ntt = 0; ntt < 4; ntt++) {
        int hi = 16 * mt + g, kr = 8 * ntt + 2 * t;
        float v0 = (oc[mt][ntt][0] + Om[wm * 2048 + hi * 32 + kr]) * inv[ntt][0];
        float v1 = (oc[mt][ntt][1] + Om[wm * 2048 + hi * 32 + kr + 1]) * inv[ntt][1];
        float v2 = (oc[mt][ntt][2] + Om[wm * 2048 + (hi + 8) * 32 + kr]) * inv[ntt][0];
        float v3 = (oc[mt][ntt][3] + Om[wm * 2048 + (hi + 8) * 32 + kr + 1]) * inv[ntt][1];
        out[obase + (size_t)kr * H_ + hi]           = v0;
        out[obase + (size_t)(kr + 1) * H_ + hi]     = v1;
        out[obase + (size_t)kr * H_ + hi + 8]       = v2;
        out[obase + (size_t)(kr + 1) * H_ + hi + 8] = v3;
      }
  }
}

extern "C" void kernel_launch(void* const* d_in, const int* in_sizes, int n_in,
                              void* d_out, int out_size) {
  const float* x  = (const float*)d_in[0];
  const float* Wk = (const float*)d_in[1];
  const float* bk = (const float*)d_in[2];
  const float* Wq = (const float*)d_in[3];
  const float* bq = (const float*)d_in[4];
  const float* Wv = (const float*)d_in[5];
  const float* bv = (const float*)d_in[6];
  float* out = (float*)d_out;

  static bool attr_set = false;
  if (!attr_set) {
    cudaFuncSetAttribute(qkv_kernel, cudaFuncAttributeMaxDynamicSharedMemorySize,
                         QKV_SMEM_BYTES);
    cudaFuncSetAttribute(attn_kernel, cudaFuncAttributeMaxDynamicSharedMemorySize,
                         ATTN_SMEM_BYTES);
    attr_set = true;
  }

  prep_w_kernel<<<24, 256>>>(Wk, Wq, Wv);
  qkv_kernel<<<(B_ * T_) / 128, 256, QKV_SMEM_BYTES>>>(x, bk, bq, bv);
  dim3 attn_grid(T_ / 128, B_);
  attn_kernel<<<attn_grid, 256, ATTN_SMEM_BYTES>>>(out);
}